// round 6
// baseline (speedup 1.0000x reference)
#include <cuda_runtime.h>
#include <cuda_bf16.h>

// GRU final-hidden: B=8192 independent scans, T<=2048, I=1, H=3.
// TWO batch elements per thread (4096 threads, 128 warps): with <1 warp/SMSP
// nothing else hides the tanh-chain latency, so we provide the ILP ourselves.
// The two elements' recurrences are independent; their instructions interleave
// and the per-warp MUFU cost per step is unchanged (18 TANH / 2 steps).
// Activations: tanh.approx.f32; sigmoid(u)=0.5*tanh(0.5u)+0.5 with the 0.5
// folded into the r/z weights (verified rel_err 4.5e-7 over 2048 steps).

__device__ __forceinline__ float tanh_fast(float u) {
    float y;
    asm("tanh.approx.f32 %0, %1;" : "=f"(y) : "f"(u));
    return y;
}

__device__ __forceinline__ float fsig_acc(float u) {
    float e = __expf(-u);
    return __fdividef(1.0f, 1.0f + e);
}

__global__ __launch_bounds__(64, 1) void gru_seq_kernel(
    const float* __restrict__ x,      // [B, T, 1]
    const int*   __restrict__ lens,   // [B]
    const float* __restrict__ h0,     // [B, 3]
    const float* __restrict__ Wih,    // [9, 1]
    const float* __restrict__ Whh,    // [9, 3]
    const float* __restrict__ bih,    // [9]
    const float* __restrict__ bhh,    // [9]
    float* __restrict__ out,          // [1, B, 3]
    int B, int T)
{
    int tidg  = blockIdx.x * blockDim.x + threadIdx.x;
    int halfB = B >> 1;
    if (tidg >= halfB) return;
    int b0 = tidg;              // element A
    int b1 = tidg + halfB;      // element B

    int len0 = lens[b0]; len0 = len0 < 1 ? 1 : (len0 > T ? T : len0);
    int len1 = lens[b1]; len1 = len1 < 1 ? 1 : (len1 > T ? T : len1);

    // Shared (uniform) weights; r/z pre-scaled by 0.5 for sigmoid-via-tanh.
    float wxr[3], wxz[3], wxn[3];
    float whr[3][3], whz[3][3], whn[3][3];
    float br[3], bz[3], bxn[3], bhn[3];
#pragma unroll
    for (int j = 0; j < 3; ++j) {
        wxr[j] = 0.5f * Wih[j];
        wxz[j] = 0.5f * Wih[3 + j];
        wxn[j] = Wih[6 + j];
#pragma unroll
        for (int k = 0; k < 3; ++k) {
            whr[j][k] = 0.5f * Whh[j * 3 + k];
            whz[j][k] = 0.5f * Whh[(3 + j) * 3 + k];
            whn[j][k] = Whh[(6 + j) * 3 + k];
        }
        br[j]  = 0.5f * (bih[j]     + bhh[j]);
        bz[j]  = 0.5f * (bih[3 + j] + bhh[3 + j]);
        bxn[j] = bih[6 + j];
        bhn[j] = bhh[6 + j];
    }

    float hA[3], hB[3];
#pragma unroll
    for (int j = 0; j < 3; ++j) { hA[j] = h0[b0 * 3 + j]; hB[j] = h0[b1 * 3 + j]; }

    // One masked GRU step on state h given scalar input xv.
    auto stepm = [&](float* h, float xv, bool act) {
        float r[3], z[3], n[3];
#pragma unroll
        for (int j = 0; j < 3; ++j) {
            float ur = fmaf(wxr[j], xv, br[j]);
            ur = fmaf(whr[j][2], h[2], fmaf(whr[j][1], h[1], fmaf(whr[j][0], h[0], ur)));
            float uz = fmaf(wxz[j], xv, bz[j]);
            uz = fmaf(whz[j][2], h[2], fmaf(whz[j][1], h[1], fmaf(whz[j][0], h[0], uz)));
            float hn = fmaf(whn[j][2], h[2], fmaf(whn[j][1], h[1], fmaf(whn[j][0], h[0], bhn[j])));
            float xn = fmaf(wxn[j], xv, bxn[j]);
            r[j] = fmaf(tanh_fast(ur), 0.5f, 0.5f);
            z[j] = fmaf(tanh_fast(uz), 0.5f, 0.5f);
            n[j] = tanh_fast(fmaf(r[j], hn, xn));
        }
#pragma unroll
        for (int j = 0; j < 3; ++j) {
            float hnew = fmaf(z[j], h[j] - n[j], n[j]);   // n + z*(h-n)
            h[j] = act ? hnew : h[j];
        }
    };

    const float4* xpA = reinterpret_cast<const float4*>(x + (size_t)b0 * T);
    const float4* xpB = reinterpret_cast<const float4*>(x + (size_t)b1 * T);
    int lenMax = len0 > len1 ? len0 : len1;
    int nC = (lenMax + 3) >> 2;

    float4 curA = xpA[0];
    float4 curB = xpB[0];
    for (int c = 0; c < nC; ++c) {
        float4 nxtA = (c + 1 < nC) ? xpA[c + 1] : curA;
        float4 nxtB = (c + 1 < nC) ? xpB[c + 1] : curB;
        float xsA[4] = {curA.x, curA.y, curA.z, curA.w};
        float xsB[4] = {curB.x, curB.y, curB.z, curB.w};
#pragma unroll
        for (int k = 0; k < 4; ++k) {
            int t = 4 * c + k;
            // Two independent steps back-to-back: their chains interleave.
            stepm(hA, xsA[k], t < len0);
            stepm(hB, xsB[k], t < len1);
        }
        curA = nxtA;
        curB = nxtB;
    }

    // Output = sigmoid(hT), layout [1, B, H].
#pragma unroll
    for (int j = 0; j < 3; ++j) {
        out[b0 * 3 + j] = fsig_acc(hA[j]);
        out[b1 * 3 + j] = fsig_acc(hB[j]);
    }
}

extern "C" void kernel_launch(void* const* d_in, const int* in_sizes, int n_in,
                              void* d_out, int out_size)
{
    const float* x   = (const float*)d_in[0];
    const int*   len = (const int*)  d_in[1];
    const float* h0  = (const float*)d_in[2];
    const float* Wih = (const float*)d_in[3];
    const float* Whh = (const float*)d_in[4];
    const float* bih = (const float*)d_in[5];
    const float* bhh = (const float*)d_in[6];
    float* out = (float*)d_out;

    int B = in_sizes[1];            // seq_lengths is [B]
    int T = in_sizes[0] / B;        // x is [B, T, 1]

    const int block = 64;
    int threads = B >> 1;           // two elements per thread
    int grid = (threads + block - 1) / block;
    gru_seq_kernel<<<grid, block>>>(x, len, h0, Wih, Whh, bih, bhh, out, B, T);
}

// round 7
// speedup vs baseline: 1.6923x; 1.6923x over previous
#include <cuda_runtime.h>
#include <cuda_bf16.h>

// GRU final-hidden: B=8192, T<=2048, I=1, H=3.
// TWO LANES PER ELEMENT. Binding resource (measured R4 vs R6) is MUFU.TANH
// throughput per warp (rt~16/SMSP): 9 TANH/step = 144 cyc/step floor at one
// element per lane. Splitting each element's 9 activations 5/4 across a lane
// pair (role-uniform code, role-selected weight registers) cuts the warp to
// 5 TANH/step = 80 cyc. 512 warps still <= 592 SMSPs: one warp per SMSP.
//
// Role 0 tanh set: r0, r1, z2(dup), n0, n1
// Role 1 tanh set: z0, z1, z2,      r2, n2
// Exchange per step: 4x shfl.bfly(1), each issued as soon as ready.
// sigmoid(u) = 0.5*tanh(0.5u)+0.5 with the 0.5 folded into weights.

__device__ __forceinline__ float tanh_fast(float u) {
    float y;
    asm("tanh.approx.f32 %0, %1;" : "=f"(y) : "f"(u));
    return y;
}

__device__ __forceinline__ float fsig_acc(float u) {
    float e = __expf(-u);
    return __fdividef(1.0f, 1.0f + e);
}

__global__ __launch_bounds__(64, 1) void gru_seq_kernel(
    const float* __restrict__ x,      // [B, T, 1]
    const int*   __restrict__ lens,   // [B]
    const float* __restrict__ h0,     // [B, 3]
    const float* __restrict__ Wih,    // [9, 1]
    const float* __restrict__ Whh,    // [9, 3]
    const float* __restrict__ bih,    // [9]
    const float* __restrict__ bhh,    // [9]
    float* __restrict__ out,          // [1, B, 3]
    int B, int T)
{
    int gt   = blockIdx.x * blockDim.x + threadIdx.x;   // 2*B threads
    int e    = gt >> 1;
    int role = gt & 1;                                  // == lane parity
    bool store_ok = (e < B);
    if (e >= B) e = B - 1;    // keep warp full for shfl.sync

    int len = lens[e];
    len = len < 1 ? 1 : (len > T ? T : len);

    // ---- role-selected weight registers (loaded once) ----
    // Gate row g of Whh is Whh[g*3 + k]; r rows 0-2, z rows 3-5, n rows 6-8.
    // Phase-1 rows (sigmoid args, pre-scaled 0.5): role0 {r0, r1, z2}, role1 {z0, z1, z2}.
    int p1idx[3];
    if (role == 0) { p1idx[0] = 0; p1idx[1] = 1; p1idx[2] = 5; }
    else           { p1idx[0] = 3; p1idx[1] = 4; p1idx[2] = 5; }
    float p1wx[3], p1w[3][3], p1b[3];
#pragma unroll
    for (int i = 0; i < 3; ++i) {
        int g = p1idx[i];
        p1wx[i] = 0.5f * Wih[g];
#pragma unroll
        for (int k = 0; k < 3; ++k) p1w[i][k] = 0.5f * Whh[g * 3 + k];
        p1b[i] = 0.5f * (bih[g] + bhh[g]);
    }
    // Q1 (h-projection for first n-stage): role0 hn0 (row 6), role1 hn2 (row 8).
    int q1g = role ? 8 : 6;
    float q1w0 = Whh[q1g * 3 + 0], q1w1 = Whh[q1g * 3 + 1], q1w2 = Whh[q1g * 3 + 2];
    float q1b  = bhh[q1g];
    // S1: role0 = xn0 (x-only, h-weights 0); role1 = 0.5*u_r2 (full projection).
    float s1x, s1w0, s1w1, s1w2, s1b;
    if (role == 0) { s1x = Wih[6]; s1w0 = s1w1 = s1w2 = 0.f; s1b = bih[6]; }
    else { s1x = 0.5f * Wih[2]; s1w0 = 0.5f * Whh[6]; s1w1 = 0.5f * Whh[7];
           s1w2 = 0.5f * Whh[8]; s1b = 0.5f * (bih[2] + bhh[2]); }
    // Q2: role0 hn1 (row 7), role1 hn2 (row 8, recomputed).
    int q2g = role ? 8 : 7;
    float q2w0 = Whh[q2g * 3 + 0], q2w1 = Whh[q2g * 3 + 1], q2w2 = Whh[q2g * 3 + 2];
    float q2b  = bhh[q2g];
    // S2 (x-only xn): role0 xn1 (row 7), role1 xn2 (row 8).
    int s2g = role ? 8 : 7;
    float s2x = Wih[s2g], s2b = bih[s2g];
    // c1: D1-stage r-multiplier: role0 r0 = 0.5*A1+0.5; role1 forces P1=0.
    float c1 = role ? 0.0f : 0.5f;

    float h0r = h0[e * 3 + 0], h1r = h0[e * 3 + 1], h2r = h0[e * 3 + 2];

    // warp-uniform trip count (shfl.sync safety)
    int nC = (len + 3) >> 2;
    int nCmax = __reduce_max_sync(0xffffffffu, nC);

    const float4* xp = reinterpret_cast<const float4*>(x + (size_t)e * T);
    float4 cur = xp[0];

    for (int c = 0; c < nCmax; ++c) {
        float4 nxt = (c + 1 < nCmax) ? xp[c + 1] : cur;
        float xs[4] = {cur.x, cur.y, cur.z, cur.w};
#pragma unroll
        for (int k = 0; k < 4; ++k) {
            float xv = xs[k];
            int   t  = 4 * c + k;
            bool act = t < len;

            // phase 1: three sigmoid-style tanh args
            float u1 = fmaf(p1wx[0], xv, p1b[0]);
            u1 = fmaf(p1w[0][2], h2r, fmaf(p1w[0][1], h1r, fmaf(p1w[0][0], h0r, u1)));
            float u2 = fmaf(p1wx[1], xv, p1b[1]);
            u2 = fmaf(p1w[1][2], h2r, fmaf(p1w[1][1], h1r, fmaf(p1w[1][0], h0r, u2)));
            float u3 = fmaf(p1wx[2], xv, p1b[2]);
            u3 = fmaf(p1w[2][2], h2r, fmaf(p1w[2][1], h1r, fmaf(p1w[2][0], h0r, u3)));
            float A1 = tanh_fast(u1);
            float A2 = tanh_fast(u2);
            float A3 = tanh_fast(u3);

            // stage D1: role0 n0 = tanh(r0*hn0 + xn0); role1 r2t = tanh(0.5*u_r2)
            float Q1v = fmaf(q1w2, h2r, fmaf(q1w1, h1r, fmaf(q1w0, h0r, q1b)));
            float S1v = fmaf(s1x, xv, s1b);
            S1v = fmaf(s1w2, h2r, fmaf(s1w1, h1r, fmaf(s1w0, h0r, S1v)));
            float P1 = fmaf(A1, c1, c1);                 // role0: r0; role1: 0
            float D1 = tanh_fast(fmaf(P1, Q1v, S1v));

            // stage E: role0 n1 = tanh(r1*hn1 + xn1); role1 n2 = tanh(r2*hn2 + xn2)
            float Q2v = fmaf(q2w2, h2r, fmaf(q2w1, h1r, fmaf(q2w0, h0r, q2b)));
            float S2v = fmaf(s2x, xv, s2b);
            float P2in = role ? D1 : A2;
            float P2 = fmaf(P2in, 0.5f, 0.5f);           // r1 / r2
            float E  = tanh_fast(fmaf(P2, Q2v, S2v));

            // exchange (each bfly fires as soon as its source is ready)
            float g1 = __shfl_xor_sync(0xffffffffu, A1, 1);  // role0 <- z0t
            float g2 = __shfl_xor_sync(0xffffffffu, A2, 1);  // role0 <- z1t
            float g3 = __shfl_xor_sync(0xffffffffu, D1, 1);  // role1 <- n0
            float g4 = __shfl_xor_sync(0xffffffffu, E,  1);  // role0<-n2, role1<-n1

            float z0t = role ? A1 : g1;
            float z1t = role ? A2 : g2;
            float z2t = A3;
            float n0  = role ? g3 : D1;
            float n1  = role ? g4 : E;
            float n2  = role ? E  : g4;

            // update h' = n + z*(h-n), frozen after len
            float z0 = fmaf(z0t, 0.5f, 0.5f);
            float z1 = fmaf(z1t, 0.5f, 0.5f);
            float z2 = fmaf(z2t, 0.5f, 0.5f);
            float nh0 = fmaf(z0, h0r - n0, n0);
            float nh1 = fmaf(z1, h1r - n1, n1);
            float nh2 = fmaf(z2, h2r - n2, n2);
            h0r = act ? nh0 : h0r;
            h1r = act ? nh1 : h1r;
            h2r = act ? nh2 : h2r;
        }
        cur = nxt;
    }

    if (role == 0 && store_ok) {
        out[e * 3 + 0] = fsig_acc(h0r);
        out[e * 3 + 1] = fsig_acc(h1r);
        out[e * 3 + 2] = fsig_acc(h2r);
    }
}

extern "C" void kernel_launch(void* const* d_in, const int* in_sizes, int n_in,
                              void* d_out, int out_size)
{
    const float* x   = (const float*)d_in[0];
    const int*   len = (const int*)  d_in[1];
    const float* h0  = (const float*)d_in[2];
    const float* Wih = (const float*)d_in[3];
    const float* Whh = (const float*)d_in[4];
    const float* bih = (const float*)d_in[5];
    const float* bhh = (const float*)d_in[6];
    float* out = (float*)d_out;

    int B = in_sizes[1];            // seq_lengths is [B]
    int T = in_sizes[0] / B;        // x is [B, T, 1]

    const int block = 64;
    int threads = B * 2;            // two lanes per element
    int grid = (threads + block - 1) / block;
    gru_seq_kernel<<<grid, block>>>(x, len, h0, Wih, Whh, bih, bhh, out, B, T);
}